// round 7
// baseline (speedup 1.0000x reference)
#include <cuda_runtime.h>
#include <math.h>

#define N_NODES 50000
#define N_EDGES 800000
#define IN_C    64
#define HID     128
#define OUT_C   2
#define N_GRAPHS 64

// ---------------- scratch ----------------
__device__ __align__(16) int   g_cnt_e [N_NODES];
__device__ float g_dinv  [N_NODES];
__device__ int   g_off   [N_NODES + 1];
__device__ int   g_cursor[N_NODES];
__device__ int2  g_csr2  [N_EDGES];        // {src, bit-cast dinv[src]}
__device__ float g_h     [N_NODES * HID];
__device__ float g_pool  [N_GRAPHS * HID];
__device__ float g_gcnt  [N_GRAPHS];

// ---------------- zero (cnt only; pool zeroed in scan) ----------------
__global__ void k_zero() {
    int i = blockIdx.x * blockDim.x + threadIdx.x;
    if (i < N_NODES) g_cnt_e[i] = 0;
}

// ---------------- degree (8 edges/thread) ----------------
__global__ void k_deg8(const int* __restrict__ dst) {
    int i8 = blockIdx.x * blockDim.x + threadIdx.x;
    if (i8 >= N_EDGES / 8) return;
    int4 a = ((const int4*)dst)[i8 * 2];
    int4 b = ((const int4*)dst)[i8 * 2 + 1];
    atomicAdd(&g_cnt_e[a.x], 1);
    atomicAdd(&g_cnt_e[a.y], 1);
    atomicAdd(&g_cnt_e[a.z], 1);
    atomicAdd(&g_cnt_e[a.w], 1);
    atomicAdd(&g_cnt_e[b.x], 1);
    atomicAdd(&g_cnt_e[b.y], 1);
    atomicAdd(&g_cnt_e[b.z], 1);
    atomicAdd(&g_cnt_e[b.w], 1);
}

// ---------------- single-block exclusive scan, 4 elems/thread + pool zero ----
__global__ void __launch_bounds__(1024) k_scan() {
    __shared__ int wsum[32];
    __shared__ int s_carry;
    int t = threadIdx.x, lane = t & 31, w = t >> 5;
    for (int i = t; i < N_GRAPHS * HID; i += 1024) g_pool[i] = 0.f;
    if (t < N_GRAPHS) g_gcnt[t] = 0.f;
    if (t == 0) s_carry = 0;
    __syncthreads();
    for (int base = 0; base < N_NODES; base += 4096) {
        int i = base + t * 4;
        int4 v = make_int4(0, 0, 0, 0);
        if (i < N_NODES) v = *(const int4*)&g_cnt_e[i];
        int s = v.x + v.y + v.z + v.w;
        int x = s;
        #pragma unroll
        for (int d = 1; d < 32; d <<= 1) {
            int y = __shfl_up_sync(0xffffffffu, x, d);
            if (lane >= d) x += y;
        }
        if (lane == 31) wsum[w] = x;
        __syncthreads();
        if (w == 0) {
            int y = wsum[lane];
            #pragma unroll
            for (int d = 1; d < 32; d <<= 1) {
                int z = __shfl_up_sync(0xffffffffu, y, d);
                if (lane >= d) y += z;
            }
            wsum[lane] = y;
        }
        __syncthreads();
        int excl = s_carry + (w ? wsum[w - 1] : 0) + x - s;
        if (i < N_NODES) {   // N_NODES % 4 == 0
            int o0 = excl, o1 = o0 + v.x, o2 = o1 + v.y, o3 = o2 + v.z;
            g_off[i]   = o0; g_off[i+1]   = o1; g_off[i+2]   = o2; g_off[i+3]   = o3;
            g_cursor[i]= o0; g_cursor[i+1]= o1; g_cursor[i+2]= o2; g_cursor[i+3]= o3;
            g_dinv[i]   = rsqrtf((float)v.x + 1.0f);
            g_dinv[i+1] = rsqrtf((float)v.y + 1.0f);
            g_dinv[i+2] = rsqrtf((float)v.z + 1.0f);
            g_dinv[i+3] = rsqrtf((float)v.w + 1.0f);
        }
        __syncthreads();
        if (t == 0) s_carry += wsum[31];
        __syncthreads();
    }
    if (t == 0) g_off[N_NODES] = N_EDGES;
}

// ---------------- CSR build (8 edges/thread): slot = {src, dinv[src]} --------
__global__ void k_csr8(const int* __restrict__ src, const int* __restrict__ dst) {
    int i8 = blockIdx.x * blockDim.x + threadIdx.x;
    if (i8 >= N_EDGES / 8) return;
    int4 s0 = ((const int4*)src)[i8 * 2];
    int4 s1 = ((const int4*)src)[i8 * 2 + 1];
    int4 d0 = ((const int4*)dst)[i8 * 2];
    int4 d1 = ((const int4*)dst)[i8 * 2 + 1];
    float w0 = g_dinv[s0.x], w1 = g_dinv[s0.y], w2 = g_dinv[s0.z], w3 = g_dinv[s0.w];
    float w4 = g_dinv[s1.x], w5 = g_dinv[s1.y], w6 = g_dinv[s1.z], w7 = g_dinv[s1.w];
    int p0 = atomicAdd(&g_cursor[d0.x], 1);
    int p1 = atomicAdd(&g_cursor[d0.y], 1);
    int p2 = atomicAdd(&g_cursor[d0.z], 1);
    int p3 = atomicAdd(&g_cursor[d0.w], 1);
    int p4 = atomicAdd(&g_cursor[d1.x], 1);
    int p5 = atomicAdd(&g_cursor[d1.y], 1);
    int p6 = atomicAdd(&g_cursor[d1.z], 1);
    int p7 = atomicAdd(&g_cursor[d1.w], 1);
    g_csr2[p0] = make_int2(s0.x, __float_as_int(w0));
    g_csr2[p1] = make_int2(s0.y, __float_as_int(w1));
    g_csr2[p2] = make_int2(s0.z, __float_as_int(w2));
    g_csr2[p3] = make_int2(s0.w, __float_as_int(w3));
    g_csr2[p4] = make_int2(s1.x, __float_as_int(w4));
    g_csr2[p5] = make_int2(s1.y, __float_as_int(w5));
    g_csr2[p6] = make_int2(s1.z, __float_as_int(w6));
    g_csr2[p7] = make_int2(s1.w, __float_as_int(w7));
}

// ---------------- fused layer 1: agg(x, 64) + GEMM(K=64) + relu -> g_h -------
__global__ void __launch_bounds__(256, 4) k_fused1(const float4* __restrict__ X,
                                                   const float4* __restrict__ W4,
                                                   const float4* __restrict__ b4) {
    __shared__ __align__(16) float4 sA[64 * 16];   // 16 KB
    __shared__ __align__(16) float4 sW[64 * 32];   // 32 KB
    int t = threadIdx.x, lane = t & 31, w = t >> 5;
    int row0 = blockIdx.x * 64;

    for (int i = t; i < 64 * 32; i += 256) sW[i] = W4[i];

    // aggregation: warp per node, half-warps interleave edges (1 edge/iter/half)
    int c = lane & 15, half = lane >> 4;
    #pragma unroll 1
    for (int it = 0; it < 8; it++) {
        int n = row0 + it * 8 + w;
        if (n < N_NODES) {
            float dn = g_dinv[n];
            float4 acc = make_float4(0.f, 0.f, 0.f, 0.f);
            if (half == 0) {
                float4 v = X[(size_t)n * 16 + c];
                acc.x = dn * v.x; acc.y = dn * v.y; acc.z = dn * v.z; acc.w = dn * v.w;
            }
            int e  = g_off[n] + half;
            int e1 = g_off[n + 1];
            for (; e + 2 < e1; e += 4) {          // 2 edges per half-lane per iter
                int2 p0 = g_csr2[e], p1 = g_csr2[e + 2];
                float4 v0 = X[(size_t)p0.x * 16 + c];
                float4 v1 = X[(size_t)p1.x * 16 + c];
                float w0 = __int_as_float(p0.y), w1 = __int_as_float(p1.y);
                acc.x += w0 * v0.x + w1 * v1.x;
                acc.y += w0 * v0.y + w1 * v1.y;
                acc.z += w0 * v0.z + w1 * v1.z;
                acc.w += w0 * v0.w + w1 * v1.w;
            }
            for (; e < e1; e += 2) {
                int2 p = g_csr2[e];
                float ws = __int_as_float(p.y);
                float4 v = X[(size_t)p.x * 16 + c];
                acc.x += ws * v.x; acc.y += ws * v.y; acc.z += ws * v.z; acc.w += ws * v.w;
            }
            acc.x += __shfl_xor_sync(0xffffffffu, acc.x, 16);
            acc.y += __shfl_xor_sync(0xffffffffu, acc.y, 16);
            acc.z += __shfl_xor_sync(0xffffffffu, acc.z, 16);
            acc.w += __shfl_xor_sync(0xffffffffu, acc.w, 16);
            if (half == 0) {
                acc.x *= dn; acc.y *= dn; acc.z *= dn; acc.w *= dn;
                sA[(it * 8 + w) * 16 + c] = acc;
            }
        } else if (half == 0) {
            sA[(it * 8 + w) * 16 + c] = make_float4(0.f, 0.f, 0.f, 0.f);
        }
    }
    __syncthreads();

    int tx = t & 31, ty = t >> 5;
    float acc[8][4];
    #pragma unroll
    for (int rr = 0; rr < 8; rr++)
        #pragma unroll
        for (int cc = 0; cc < 4; cc++) acc[rr][cc] = 0.f;

    #pragma unroll
    for (int k4 = 0; k4 < 16; k4++) {
        float4 w0 = sW[(k4 * 4 + 0) * 32 + tx];
        float4 w1 = sW[(k4 * 4 + 1) * 32 + tx];
        float4 w2 = sW[(k4 * 4 + 2) * 32 + tx];
        float4 w3 = sW[(k4 * 4 + 3) * 32 + tx];
        #pragma unroll
        for (int rr = 0; rr < 8; rr++) {
            float4 a = sA[(ty + rr * 8) * 16 + k4];
            acc[rr][0] += a.x * w0.x + a.y * w1.x + a.z * w2.x + a.w * w3.x;
            acc[rr][1] += a.x * w0.y + a.y * w1.y + a.z * w2.y + a.w * w3.y;
            acc[rr][2] += a.x * w0.z + a.y * w1.z + a.z * w2.z + a.w * w3.z;
            acc[rr][3] += a.x * w0.w + a.y * w1.w + a.z * w2.w + a.w * w3.w;
        }
    }

    float4 bb = b4[tx];
    #pragma unroll
    for (int rr = 0; rr < 8; rr++) {
        int gr = row0 + ty + rr * 8;
        if (gr < N_NODES) {
            float4 o;
            o.x = fmaxf(acc[rr][0] + bb.x, 0.f);
            o.y = fmaxf(acc[rr][1] + bb.y, 0.f);
            o.z = fmaxf(acc[rr][2] + bb.z, 0.f);
            o.w = fmaxf(acc[rr][3] + bb.w, 0.f);
            ((float4*)g_h)[(size_t)gr * 32 + tx] = o;
        }
    }
}

// ---------------- fused layer 2: agg(g_h,128) + GEMM(K=128) + mean-pool ------
__global__ void __launch_bounds__(256, 4) k_fused2(const float4* __restrict__ W4,
                                                   const float4* __restrict__ b4,
                                                   const int* __restrict__ batch) {
    __shared__ __align__(16) float4 sA[64 * 32];   // 32 KB
    __shared__ __align__(16) float4 sW[32 * 32];   // 16 KB
    int t = threadIdx.x, lane = t & 31, w = t >> 5;
    int row0 = blockIdx.x * 64;
    const float4* H = (const float4*)g_h;

    #pragma unroll 1
    for (int it = 0; it < 8; it++) {
        int n = row0 + it * 8 + w;
        if (n < N_NODES) {
            float dn = g_dinv[n];
            float4 v = H[(size_t)n * 32 + lane];
            float4 acc;
            acc.x = dn * v.x; acc.y = dn * v.y; acc.z = dn * v.z; acc.w = dn * v.w;
            int e  = g_off[n];
            int e1 = g_off[n + 1];
            for (; e + 1 < e1; e += 2) {
                int2 p0 = g_csr2[e], p1 = g_csr2[e + 1];
                float4 v0 = H[(size_t)p0.x * 32 + lane];
                float4 v1 = H[(size_t)p1.x * 32 + lane];
                float w0 = __int_as_float(p0.y), w1 = __int_as_float(p1.y);
                acc.x += w0 * v0.x + w1 * v1.x;
                acc.y += w0 * v0.y + w1 * v1.y;
                acc.z += w0 * v0.z + w1 * v1.z;
                acc.w += w0 * v0.w + w1 * v1.w;
            }
            if (e < e1) {
                int2 p = g_csr2[e];
                float ws = __int_as_float(p.y);
                float4 v0 = H[(size_t)p.x * 32 + lane];
                acc.x += ws * v0.x; acc.y += ws * v0.y; acc.z += ws * v0.z; acc.w += ws * v0.w;
            }
            acc.x *= dn; acc.y *= dn; acc.z *= dn; acc.w *= dn;
            sA[(it * 8 + w) * 32 + lane] = acc;
        } else {
            sA[(it * 8 + w) * 32 + lane] = make_float4(0.f, 0.f, 0.f, 0.f);
        }
    }

    int tx = t & 31, ty = t >> 5;
    float acc[8][4];
    #pragma unroll
    for (int rr = 0; rr < 8; rr++)
        #pragma unroll
        for (int cc = 0; cc < 4; cc++) acc[rr][cc] = 0.f;

    for (int kt = 0; kt < 128; kt += 32) {
        __syncthreads();
        for (int i = t; i < 32 * 32; i += 256) sW[i] = W4[kt * 32 + i];
        __syncthreads();
        #pragma unroll
        for (int k4 = 0; k4 < 8; k4++) {
            float4 w0 = sW[(k4 * 4 + 0) * 32 + tx];
            float4 w1 = sW[(k4 * 4 + 1) * 32 + tx];
            float4 w2 = sW[(k4 * 4 + 2) * 32 + tx];
            float4 w3 = sW[(k4 * 4 + 3) * 32 + tx];
            #pragma unroll
            for (int rr = 0; rr < 8; rr++) {
                float4 a = sA[(ty + rr * 8) * 32 + (kt >> 2) + k4];
                acc[rr][0] += a.x * w0.x + a.y * w1.x + a.z * w2.x + a.w * w3.x;
                acc[rr][1] += a.x * w0.y + a.y * w1.y + a.z * w2.y + a.w * w3.y;
                acc[rr][2] += a.x * w0.z + a.y * w1.z + a.z * w2.z + a.w * w3.z;
                acc[rr][3] += a.x * w0.w + a.y * w1.w + a.z * w2.w + a.w * w3.w;
            }
        }
    }
    __syncthreads();

    float4 bb = b4[tx];
    #pragma unroll
    for (int rr = 0; rr < 8; rr++) {
        float4 o;
        o.x = acc[rr][0] + bb.x;
        o.y = acc[rr][1] + bb.y;
        o.z = acc[rr][2] + bb.z;
        o.w = acc[rr][3] + bb.w;
        sA[(ty + rr * 8) * 32 + tx] = o;
    }
    __syncthreads();

    const float* sAf = (const float*)sA;
    int j = t & 127, half = t >> 7;
    int rbeg = half * 32;
    int rend = min(rbeg + 32, N_NODES - row0);
    float pacc = 0.f;
    int cur = -1, cnt = 0;
    for (int r = rbeg; r < rend; r++) {
        int b = __ldg(&batch[row0 + r]);
        if (b != cur) {
            if (cur >= 0) {
                atomicAdd(&g_pool[cur * HID + j], pacc);
                if (j == 0) atomicAdd(&g_gcnt[cur], (float)cnt);
            }
            cur = b; pacc = 0.f; cnt = 0;
        }
        pacc += sAf[r * 128 + j];
        cnt++;
    }
    if (cur >= 0) {
        atomicAdd(&g_pool[cur * HID + j], pacc);
        if (j == 0) atomicAdd(&g_gcnt[cur], (float)cnt);
    }
}

// ---------------- fused MLP head ----------------
__global__ void __launch_bounds__(128) k_mlp(const float* __restrict__ Wm1,
                                             const float* __restrict__ bm1,
                                             const float* __restrict__ Wm2,
                                             const float* __restrict__ bm2,
                                             float* __restrict__ out) {
    __shared__ float grow[HID];
    __shared__ float r0[HID], r1[HID];
    int r = blockIdx.x;
    int j = threadIdx.x;
    grow[j] = g_pool[r * HID + j] / fmaxf(g_gcnt[r], 1.0f);
    __syncthreads();
    float acc = bm1[j];
    #pragma unroll 8
    for (int k = 0; k < HID; k++) acc += grow[k] * Wm1[k * HID + j];
    float h = fmaxf(acc, 0.f);
    r0[j] = h * Wm2[j * OUT_C + 0];
    r1[j] = h * Wm2[j * OUT_C + 1];
    __syncthreads();
    #pragma unroll
    for (int s = 64; s > 0; s >>= 1) {
        if (j < s) { r0[j] += r0[j + s]; r1[j] += r1[j + s]; }
        __syncthreads();
    }
    if (j == 0) {
        out[r * OUT_C + 0] = r0[0] + bm2[0];
        out[r * OUT_C + 1] = r1[0] + bm2[1];
    }
}

// ---------------- launch ----------------
static inline int cdiv(int a, int b) { return (a + b - 1) / b; }

extern "C" void kernel_launch(void* const* d_in, const int* in_sizes, int n_in,
                              void* d_out, int out_size) {
    const float* x    = (const float*)d_in[0];
    const int*   ei   = (const int*)d_in[1];
    const int*   src  = ei;
    const int*   dst  = ei + N_EDGES;
    const int*   batch= (const int*)d_in[2];
    const float* W1  = (const float*)d_in[3];
    const float* b1  = (const float*)d_in[4];
    const float* W2  = (const float*)d_in[5];
    const float* b2  = (const float*)d_in[6];
    const float* Wm1 = (const float*)d_in[7];
    const float* bm1 = (const float*)d_in[8];
    const float* Wm2 = (const float*)d_in[9];
    const float* bm2 = (const float*)d_in[10];
    float* out = (float*)d_out;

    const int T = 256;

    k_zero<<<cdiv(N_NODES, T), T>>>();
    k_deg8<<<cdiv(N_EDGES / 8, T), T>>>(dst);
    k_scan<<<1, 1024>>>();
    k_csr8<<<cdiv(N_EDGES / 8, T), T>>>(src, dst);

    k_fused1<<<cdiv(N_NODES, 64), 256>>>((const float4*)x, (const float4*)W1,
                                         (const float4*)b1);
    k_fused2<<<cdiv(N_NODES, 64), 256>>>((const float4*)W2, (const float4*)b2, batch);

    k_mlp<<<N_GRAPHS, HID>>>(Wm1, bm1, Wm2, bm2, out);
}

// round 8
// speedup vs baseline: 1.0327x; 1.0327x over previous
#include <cuda_runtime.h>
#include <cuda_fp16.h>
#include <math.h>

#define N_NODES 50000
#define N_EDGES 800000
#define IN_C    64
#define HID     128
#define OUT_C   2
#define N_GRAPHS 64

// ---------------- scratch ----------------
__device__ __align__(16) int   g_cnt_e [N_NODES];
__device__ float g_dinv  [N_NODES];
__device__ int   g_off   [N_NODES + 1];
__device__ int   g_cursor[N_NODES];
__device__ int   g_csr   [N_EDGES];
__device__ uint2 g_x16   [N_NODES * 16];   // x as half: 64 feats = 16 uint2
__device__ uint2 g_h16   [N_NODES * 32];   // h as half: 128 feats = 32 uint2
__device__ float g_pool  [N_GRAPHS * HID];
__device__ float g_gcnt  [N_GRAPHS];

// ---------------- helpers ----------------
__device__ __forceinline__ float4 h4_to_f4(uint2 u) {
    __half2 a = *(__half2*)&u.x;
    __half2 b = *(__half2*)&u.y;
    float2 fa = __half22float2(a);
    float2 fb = __half22float2(b);
    return make_float4(fa.x, fa.y, fb.x, fb.y);
}
__device__ __forceinline__ uint2 f4_to_h4(float4 v) {
    __half2 a = __floats2half2_rn(v.x, v.y);
    __half2 b = __floats2half2_rn(v.z, v.w);
    uint2 u;
    u.x = *(unsigned*)&a;
    u.y = *(unsigned*)&b;
    return u;
}

// ---------------- zero (cnt only; pool zeroed in scan) ----------------
__global__ void k_zero() {
    int i = blockIdx.x * blockDim.x + threadIdx.x;
    if (i < N_NODES) g_cnt_e[i] = 0;
}

// ---------------- x -> half ----------------
__global__ void k_x16(const float4* __restrict__ X4) {
    int i = blockIdx.x * blockDim.x + threadIdx.x;
    if (i >= N_NODES * 16) return;
    g_x16[i] = f4_to_h4(X4[i]);
}

// ---------------- degree (4 edges/thread) ----------------
__global__ void k_deg4(const int* __restrict__ dst) {
    int i4 = blockIdx.x * blockDim.x + threadIdx.x;
    if (i4 >= N_EDGES / 4) return;
    int4 d = ((const int4*)dst)[i4];
    atomicAdd(&g_cnt_e[d.x], 1);
    atomicAdd(&g_cnt_e[d.y], 1);
    atomicAdd(&g_cnt_e[d.z], 1);
    atomicAdd(&g_cnt_e[d.w], 1);
}

// ---------------- single-block exclusive scan, 4 elems/thread + pool zero ----
__global__ void __launch_bounds__(1024) k_scan() {
    __shared__ int wsum[32];
    __shared__ int s_carry;
    int t = threadIdx.x, lane = t & 31, w = t >> 5;
    for (int i = t; i < N_GRAPHS * HID; i += 1024) g_pool[i] = 0.f;
    if (t < N_GRAPHS) g_gcnt[t] = 0.f;
    if (t == 0) s_carry = 0;
    __syncthreads();
    for (int base = 0; base < N_NODES; base += 4096) {
        int i = base + t * 4;
        int4 v = make_int4(0, 0, 0, 0);
        if (i < N_NODES) v = *(const int4*)&g_cnt_e[i];
        int s = v.x + v.y + v.z + v.w;
        int x = s;
        #pragma unroll
        for (int d = 1; d < 32; d <<= 1) {
            int y = __shfl_up_sync(0xffffffffu, x, d);
            if (lane >= d) x += y;
        }
        if (lane == 31) wsum[w] = x;
        __syncthreads();
        if (w == 0) {
            int y = wsum[lane];
            #pragma unroll
            for (int d = 1; d < 32; d <<= 1) {
                int z = __shfl_up_sync(0xffffffffu, y, d);
                if (lane >= d) y += z;
            }
            wsum[lane] = y;
        }
        __syncthreads();
        int excl = s_carry + (w ? wsum[w - 1] : 0) + x - s;
        if (i < N_NODES) {   // N_NODES % 4 == 0
            int o0 = excl, o1 = o0 + v.x, o2 = o1 + v.y, o3 = o2 + v.z;
            g_off[i]   = o0; g_off[i+1]   = o1; g_off[i+2]   = o2; g_off[i+3]   = o3;
            g_cursor[i]= o0; g_cursor[i+1]= o1; g_cursor[i+2]= o2; g_cursor[i+3]= o3;
            g_dinv[i]   = rsqrtf((float)v.x + 1.0f);
            g_dinv[i+1] = rsqrtf((float)v.y + 1.0f);
            g_dinv[i+2] = rsqrtf((float)v.z + 1.0f);
            g_dinv[i+3] = rsqrtf((float)v.w + 1.0f);
        }
        __syncthreads();
        if (t == 0) s_carry += wsum[31];
        __syncthreads();
    }
    if (t == 0) g_off[N_NODES] = N_EDGES;
}

// ---------------- CSR build (4 edges/thread) ----------------
__global__ void k_csr4(const int* __restrict__ src, const int* __restrict__ dst) {
    int i4 = blockIdx.x * blockDim.x + threadIdx.x;
    if (i4 >= N_EDGES / 4) return;
    int4 s = ((const int4*)src)[i4];
    int4 d = ((const int4*)dst)[i4];
    int p0 = atomicAdd(&g_cursor[d.x], 1);
    int p1 = atomicAdd(&g_cursor[d.y], 1);
    int p2 = atomicAdd(&g_cursor[d.z], 1);
    int p3 = atomicAdd(&g_cursor[d.w], 1);
    g_csr[p0] = s.x; g_csr[p1] = s.y; g_csr[p2] = s.z; g_csr[p3] = s.w;
}

// ---------------- fused layer 1: agg(x16, 64) + GEMM(K=64) + relu -> g_h16 ---
__global__ void __launch_bounds__(256) k_fused1(const float4* __restrict__ W4,
                                                const float4* __restrict__ b4) {
    __shared__ __align__(16) float4 sA[64 * 16];   // 16 KB
    __shared__ __align__(16) float4 sW[64 * 32];   // 32 KB
    int t = threadIdx.x, lane = t & 31, w = t >> 5;
    int row0 = blockIdx.x * 64;

    for (int i = t; i < 64 * 32; i += 256) sW[i] = W4[i];

    // aggregation: warp per node, half-warps interleave edges
    int c = lane & 15, half = lane >> 4;
    #pragma unroll 1
    for (int it = 0; it < 8; it++) {
        int n = row0 + it * 8 + w;
        if (n < N_NODES) {
            float dn = g_dinv[n];
            float4 acc = make_float4(0.f, 0.f, 0.f, 0.f);
            if (half == 0) {
                float4 v = h4_to_f4(g_x16[(size_t)n * 16 + c]);
                acc.x = dn * v.x; acc.y = dn * v.y; acc.z = dn * v.z; acc.w = dn * v.w;
            }
            int e  = g_off[n] + half;
            int e1 = g_off[n + 1];
            for (; e < e1; e += 2) {
                int s = g_csr[e];
                float ds = g_dinv[s];
                float4 v = h4_to_f4(g_x16[(size_t)s * 16 + c]);
                acc.x += ds * v.x; acc.y += ds * v.y; acc.z += ds * v.z; acc.w += ds * v.w;
            }
            acc.x += __shfl_xor_sync(0xffffffffu, acc.x, 16);
            acc.y += __shfl_xor_sync(0xffffffffu, acc.y, 16);
            acc.z += __shfl_xor_sync(0xffffffffu, acc.z, 16);
            acc.w += __shfl_xor_sync(0xffffffffu, acc.w, 16);
            if (half == 0) {
                acc.x *= dn; acc.y *= dn; acc.z *= dn; acc.w *= dn;
                sA[(it * 8 + w) * 16 + c] = acc;
            }
        } else if (half == 0) {
            sA[(it * 8 + w) * 16 + c] = make_float4(0.f, 0.f, 0.f, 0.f);
        }
    }
    __syncthreads();

    int tx = t & 31, ty = t >> 5;
    float acc[8][4];
    #pragma unroll
    for (int rr = 0; rr < 8; rr++)
        #pragma unroll
        for (int cc = 0; cc < 4; cc++) acc[rr][cc] = 0.f;

    #pragma unroll
    for (int k4 = 0; k4 < 16; k4++) {
        float4 w0 = sW[(k4 * 4 + 0) * 32 + tx];
        float4 w1 = sW[(k4 * 4 + 1) * 32 + tx];
        float4 w2 = sW[(k4 * 4 + 2) * 32 + tx];
        float4 w3 = sW[(k4 * 4 + 3) * 32 + tx];
        #pragma unroll
        for (int rr = 0; rr < 8; rr++) {
            float4 a = sA[(ty + rr * 8) * 16 + k4];
            acc[rr][0] += a.x * w0.x + a.y * w1.x + a.z * w2.x + a.w * w3.x;
            acc[rr][1] += a.x * w0.y + a.y * w1.y + a.z * w2.y + a.w * w3.y;
            acc[rr][2] += a.x * w0.z + a.y * w1.z + a.z * w2.z + a.w * w3.z;
            acc[rr][3] += a.x * w0.w + a.y * w1.w + a.z * w2.w + a.w * w3.w;
        }
    }

    float4 bb = b4[tx];
    #pragma unroll
    for (int rr = 0; rr < 8; rr++) {
        int gr = row0 + ty + rr * 8;
        if (gr < N_NODES) {
            float4 o;
            o.x = fmaxf(acc[rr][0] + bb.x, 0.f);
            o.y = fmaxf(acc[rr][1] + bb.y, 0.f);
            o.z = fmaxf(acc[rr][2] + bb.z, 0.f);
            o.w = fmaxf(acc[rr][3] + bb.w, 0.f);
            g_h16[(size_t)gr * 32 + tx] = f4_to_h4(o);
        }
    }
}

// ---------------- fused layer 2: agg(g_h16,128) + GEMM(K=128) + mean-pool ----
__global__ void __launch_bounds__(256) k_fused2(const float4* __restrict__ W4,
                                                const float4* __restrict__ b4,
                                                const int* __restrict__ batch) {
    __shared__ __align__(16) float4 sA[64 * 32];   // 32 KB
    __shared__ __align__(16) float4 sW[32 * 32];   // 16 KB
    int t = threadIdx.x, lane = t & 31, w = t >> 5;
    int row0 = blockIdx.x * 64;

    // aggregation: warp per node, lane = 4-feat chunk (uint2 of halves)
    #pragma unroll 1
    for (int it = 0; it < 8; it++) {
        int n = row0 + it * 8 + w;
        if (n < N_NODES) {
            float dn = g_dinv[n];
            float4 v = h4_to_f4(g_h16[(size_t)n * 32 + lane]);
            float4 acc;
            acc.x = dn * v.x; acc.y = dn * v.y; acc.z = dn * v.z; acc.w = dn * v.w;
            int e  = g_off[n];
            int e1 = g_off[n + 1];
            for (; e + 1 < e1; e += 2) {
                int s0 = g_csr[e], s1 = g_csr[e + 1];
                float d0 = g_dinv[s0], d1 = g_dinv[s1];
                float4 v0 = h4_to_f4(g_h16[(size_t)s0 * 32 + lane]);
                float4 v1 = h4_to_f4(g_h16[(size_t)s1 * 32 + lane]);
                acc.x += d0 * v0.x + d1 * v1.x;
                acc.y += d0 * v0.y + d1 * v1.y;
                acc.z += d0 * v0.z + d1 * v1.z;
                acc.w += d0 * v0.w + d1 * v1.w;
            }
            if (e < e1) {
                int s0 = g_csr[e];
                float d0 = g_dinv[s0];
                float4 v0 = h4_to_f4(g_h16[(size_t)s0 * 32 + lane]);
                acc.x += d0 * v0.x; acc.y += d0 * v0.y; acc.z += d0 * v0.z; acc.w += d0 * v0.w;
            }
            acc.x *= dn; acc.y *= dn; acc.z *= dn; acc.w *= dn;
            sA[(it * 8 + w) * 32 + lane] = acc;
        } else {
            sA[(it * 8 + w) * 32 + lane] = make_float4(0.f, 0.f, 0.f, 0.f);
        }
    }

    int tx = t & 31, ty = t >> 5;
    float acc[8][4];
    #pragma unroll
    for (int rr = 0; rr < 8; rr++)
        #pragma unroll
        for (int cc = 0; cc < 4; cc++) acc[rr][cc] = 0.f;

    for (int kt = 0; kt < 128; kt += 32) {
        __syncthreads();
        for (int i = t; i < 32 * 32; i += 256) sW[i] = W4[kt * 32 + i];
        __syncthreads();
        #pragma unroll
        for (int k4 = 0; k4 < 8; k4++) {
            float4 w0 = sW[(k4 * 4 + 0) * 32 + tx];
            float4 w1 = sW[(k4 * 4 + 1) * 32 + tx];
            float4 w2 = sW[(k4 * 4 + 2) * 32 + tx];
            float4 w3 = sW[(k4 * 4 + 3) * 32 + tx];
            #pragma unroll
            for (int rr = 0; rr < 8; rr++) {
                float4 a = sA[(ty + rr * 8) * 32 + (kt >> 2) + k4];
                acc[rr][0] += a.x * w0.x + a.y * w1.x + a.z * w2.x + a.w * w3.x;
                acc[rr][1] += a.x * w0.y + a.y * w1.y + a.z * w2.y + a.w * w3.y;
                acc[rr][2] += a.x * w0.z + a.y * w1.z + a.z * w2.z + a.w * w3.z;
                acc[rr][3] += a.x * w0.w + a.y * w1.w + a.z * w2.w + a.w * w3.w;
            }
        }
    }
    __syncthreads();

    float4 bb = b4[tx];
    #pragma unroll
    for (int rr = 0; rr < 8; rr++) {
        float4 o;
        o.x = acc[rr][0] + bb.x;
        o.y = acc[rr][1] + bb.y;
        o.z = acc[rr][2] + bb.z;
        o.w = acc[rr][3] + bb.w;
        sA[(ty + rr * 8) * 32 + tx] = o;
    }
    __syncthreads();

    const float* sAf = (const float*)sA;
    int j = t & 127, half = t >> 7;
    int rbeg = half * 32;
    int rend = min(rbeg + 32, N_NODES - row0);
    float pacc = 0.f;
    int cur = -1, cnt = 0;
    for (int r = rbeg; r < rend; r++) {
        int b = __ldg(&batch[row0 + r]);
        if (b != cur) {
            if (cur >= 0) {
                atomicAdd(&g_pool[cur * HID + j], pacc);
                if (j == 0) atomicAdd(&g_gcnt[cur], (float)cnt);
            }
            cur = b; pacc = 0.f; cnt = 0;
        }
        pacc += sAf[r * 128 + j];
        cnt++;
    }
    if (cur >= 0) {
        atomicAdd(&g_pool[cur * HID + j], pacc);
        if (j == 0) atomicAdd(&g_gcnt[cur], (float)cnt);
    }
}

// ---------------- fused MLP head ----------------
__global__ void __launch_bounds__(128) k_mlp(const float* __restrict__ Wm1,
                                             const float* __restrict__ bm1,
                                             const float* __restrict__ Wm2,
                                             const float* __restrict__ bm2,
                                             float* __restrict__ out) {
    __shared__ float grow[HID];
    __shared__ float r0[HID], r1[HID];
    int r = blockIdx.x;
    int j = threadIdx.x;
    grow[j] = g_pool[r * HID + j] / fmaxf(g_gcnt[r], 1.0f);
    __syncthreads();
    float acc = bm1[j];
    #pragma unroll 8
    for (int k = 0; k < HID; k++) acc += grow[k] * Wm1[k * HID + j];
    float h = fmaxf(acc, 0.f);
    r0[j] = h * Wm2[j * OUT_C + 0];
    r1[j] = h * Wm2[j * OUT_C + 1];
    __syncthreads();
    #pragma unroll
    for (int s = 64; s > 0; s >>= 1) {
        if (j < s) { r0[j] += r0[j + s]; r1[j] += r1[j + s]; }
        __syncthreads();
    }
    if (j == 0) {
        out[r * OUT_C + 0] = r0[0] + bm2[0];
        out[r * OUT_C + 1] = r1[0] + bm2[1];
    }
}

// ---------------- launch ----------------
static inline int cdiv(int a, int b) { return (a + b - 1) / b; }

extern "C" void kernel_launch(void* const* d_in, const int* in_sizes, int n_in,
                              void* d_out, int out_size) {
    const float* x    = (const float*)d_in[0];
    const int*   ei   = (const int*)d_in[1];
    const int*   src  = ei;
    const int*   dst  = ei + N_EDGES;
    const int*   batch= (const int*)d_in[2];
    const float* W1  = (const float*)d_in[3];
    const float* b1  = (const float*)d_in[4];
    const float* W2  = (const float*)d_in[5];
    const float* b2  = (const float*)d_in[6];
    const float* Wm1 = (const float*)d_in[7];
    const float* bm1 = (const float*)d_in[8];
    const float* Wm2 = (const float*)d_in[9];
    const float* bm2 = (const float*)d_in[10];
    float* out = (float*)d_out;

    const int T = 256;

    k_zero<<<cdiv(N_NODES, T), T>>>();
    k_x16 <<<cdiv(N_NODES * 16, T), T>>>((const float4*)x);
    k_deg4<<<cdiv(N_EDGES / 4, T), T>>>(dst);
    k_scan<<<1, 1024>>>();
    k_csr4<<<cdiv(N_EDGES / 4, T), T>>>(src, dst);

    k_fused1<<<cdiv(N_NODES, 64), 256>>>((const float4*)W1, (const float4*)b1);
    k_fused2<<<cdiv(N_NODES, 64), 256>>>((const float4*)W2, (const float4*)b2, batch);

    k_mlp<<<N_GRAPHS, HID>>>(Wm1, bm1, Wm2, bm2, out);
}

// round 9
// speedup vs baseline: 1.3134x; 1.2719x over previous
#include <cuda_runtime.h>
#include <math.h>

#define N_NODES 50000
#define N_EDGES 800000
#define IN_C    64
#define HID     128
#define OUT_C   2
#define N_GRAPHS 64
#define SCAN_NBLK 49   // ceil(50000/1024)

// ---------------- scratch ----------------
__device__ __align__(16) int   g_cnt_e [N_NODES];
__device__ float g_dinv  [N_NODES];
__device__ int   g_off   [N_NODES + 1];
__device__ int   g_cursor[N_NODES];
__device__ int   g_csr   [N_EDGES];
__device__ int   g_part  [64];             // block partial sums (>= SCAN_NBLK)
__device__ float g_h     [N_NODES * HID];
__device__ float g_pool  [N_GRAPHS * HID];
__device__ float g_gcnt  [N_GRAPHS];

// ---------------- zero (cnt + pool) ----------------
__global__ void k_zero() {
    int i = blockIdx.x * blockDim.x + threadIdx.x;
    if (i < N_NODES) g_cnt_e[i] = 0;
    if (i < N_GRAPHS * HID) g_pool[i] = 0.f;
    if (i < N_GRAPHS) g_gcnt[i] = 0.f;
}

// ---------------- degree (4 edges/thread) ----------------
__global__ void k_deg4(const int* __restrict__ dst) {
    int i4 = blockIdx.x * blockDim.x + threadIdx.x;
    if (i4 >= N_EDGES / 4) return;
    int4 d = ((const int4*)dst)[i4];
    atomicAdd(&g_cnt_e[d.x], 1);
    atomicAdd(&g_cnt_e[d.y], 1);
    atomicAdd(&g_cnt_e[d.z], 1);
    atomicAdd(&g_cnt_e[d.w], 1);
}

// ---------------- scan pass 1: per-block sums ----------------
__global__ void __launch_bounds__(1024) k_blocksum() {
    __shared__ int ws[32];
    int t = threadIdx.x, lane = t & 31, w = t >> 5;
    int i = blockIdx.x * 1024 + t;
    int v = (i < N_NODES) ? g_cnt_e[i] : 0;
    int s = v;
    #pragma unroll
    for (int d = 16; d > 0; d >>= 1) s += __shfl_xor_sync(0xffffffffu, s, d);
    if (lane == 0) ws[w] = s;
    __syncthreads();
    if (w == 0) {
        int x = ws[lane];
        #pragma unroll
        for (int d = 16; d > 0; d >>= 1) x += __shfl_xor_sync(0xffffffffu, x, d);
        if (lane == 0) g_part[blockIdx.x] = x;
    }
}

// ---------------- scan pass 2: exclusive scan of partials (1 block) ----------
__global__ void __launch_bounds__(64) k_scanpart() {
    __shared__ int w0sum;
    int t = threadIdx.x, lane = t & 31, w = t >> 5;
    int v = (t < SCAN_NBLK) ? g_part[t] : 0;
    int x = v;
    #pragma unroll
    for (int d = 1; d < 32; d <<= 1) {
        int y = __shfl_up_sync(0xffffffffu, x, d);
        if (lane >= d) x += y;
    }
    if (w == 0 && lane == 31) w0sum = x;
    __syncthreads();
    int excl = x - v + (w == 1 ? w0sum : 0);
    if (t < SCAN_NBLK) g_part[t] = excl;
}

// ---------------- scan pass 3: local scan + offset, write off/cursor/dinv ----
__global__ void __launch_bounds__(1024) k_offsets() {
    __shared__ int ws[32];
    int t = threadIdx.x, lane = t & 31, w = t >> 5;
    int i = blockIdx.x * 1024 + t;
    int v = (i < N_NODES) ? g_cnt_e[i] : 0;
    int x = v;
    #pragma unroll
    for (int d = 1; d < 32; d <<= 1) {
        int y = __shfl_up_sync(0xffffffffu, x, d);
        if (lane >= d) x += y;
    }
    if (lane == 31) ws[w] = x;
    __syncthreads();
    if (w == 0) {
        int y = ws[lane];
        #pragma unroll
        for (int d = 1; d < 32; d <<= 1) {
            int z = __shfl_up_sync(0xffffffffu, y, d);
            if (lane >= d) y += z;
        }
        ws[lane] = y;
    }
    __syncthreads();
    int excl = g_part[blockIdx.x] + (w ? ws[w - 1] : 0) + x - v;
    if (i < N_NODES) {
        g_off[i]    = excl;
        g_cursor[i] = excl;
        g_dinv[i]   = rsqrtf((float)v + 1.0f);
    }
    if (i == 0) g_off[N_NODES] = N_EDGES;
}

// ---------------- CSR build (4 edges/thread) ----------------
__global__ void k_csr4(const int* __restrict__ src, const int* __restrict__ dst) {
    int i4 = blockIdx.x * blockDim.x + threadIdx.x;
    if (i4 >= N_EDGES / 4) return;
    int4 s = ((const int4*)src)[i4];
    int4 d = ((const int4*)dst)[i4];
    int p0 = atomicAdd(&g_cursor[d.x], 1);
    int p1 = atomicAdd(&g_cursor[d.y], 1);
    int p2 = atomicAdd(&g_cursor[d.z], 1);
    int p3 = atomicAdd(&g_cursor[d.w], 1);
    g_csr[p0] = s.x; g_csr[p1] = s.y; g_csr[p2] = s.z; g_csr[p3] = s.w;
}

// ---------------- fused layer 1: agg(x, 64) + GEMM(K=64) + relu -> g_h -------
__global__ void __launch_bounds__(256) k_fused1(const float4* __restrict__ X,
                                                const float4* __restrict__ W4,
                                                const float4* __restrict__ b4) {
    __shared__ __align__(16) float4 sA[64 * 16];   // 16 KB
    __shared__ __align__(16) float4 sW[64 * 32];   // 32 KB
    int t = threadIdx.x, lane = t & 31, w = t >> 5;
    int row0 = blockIdx.x * 64;

    for (int i = t; i < 64 * 32; i += 256) sW[i] = W4[i];

    int c = lane & 15, half = lane >> 4;
    #pragma unroll 1
    for (int it = 0; it < 8; it++) {
        int n = row0 + it * 8 + w;
        if (n < N_NODES) {
            float dn = g_dinv[n];
            float4 acc = make_float4(0.f, 0.f, 0.f, 0.f);
            if (half == 0) {
                float4 v = X[(size_t)n * 16 + c];
                acc.x = dn * v.x; acc.y = dn * v.y; acc.z = dn * v.z; acc.w = dn * v.w;
            }
            int e  = g_off[n] + half;
            int e1 = g_off[n + 1];
            for (; e < e1; e += 2) {
                int s = g_csr[e];
                float ds = g_dinv[s];
                float4 v = X[(size_t)s * 16 + c];
                acc.x += ds * v.x; acc.y += ds * v.y; acc.z += ds * v.z; acc.w += ds * v.w;
            }
            acc.x += __shfl_xor_sync(0xffffffffu, acc.x, 16);
            acc.y += __shfl_xor_sync(0xffffffffu, acc.y, 16);
            acc.z += __shfl_xor_sync(0xffffffffu, acc.z, 16);
            acc.w += __shfl_xor_sync(0xffffffffu, acc.w, 16);
            if (half == 0) {
                acc.x *= dn; acc.y *= dn; acc.z *= dn; acc.w *= dn;
                sA[(it * 8 + w) * 16 + c] = acc;
            }
        } else if (half == 0) {
            sA[(it * 8 + w) * 16 + c] = make_float4(0.f, 0.f, 0.f, 0.f);
        }
    }
    __syncthreads();

    int tx = t & 31, ty = t >> 5;
    float acc[8][4];
    #pragma unroll
    for (int rr = 0; rr < 8; rr++)
        #pragma unroll
        for (int cc = 0; cc < 4; cc++) acc[rr][cc] = 0.f;

    #pragma unroll
    for (int k4 = 0; k4 < 16; k4++) {
        float4 w0 = sW[(k4 * 4 + 0) * 32 + tx];
        float4 w1 = sW[(k4 * 4 + 1) * 32 + tx];
        float4 w2 = sW[(k4 * 4 + 2) * 32 + tx];
        float4 w3 = sW[(k4 * 4 + 3) * 32 + tx];
        #pragma unroll
        for (int rr = 0; rr < 8; rr++) {
            float4 a = sA[(ty + rr * 8) * 16 + k4];
            acc[rr][0] += a.x * w0.x + a.y * w1.x + a.z * w2.x + a.w * w3.x;
            acc[rr][1] += a.x * w0.y + a.y * w1.y + a.z * w2.y + a.w * w3.y;
            acc[rr][2] += a.x * w0.z + a.y * w1.z + a.z * w2.z + a.w * w3.z;
            acc[rr][3] += a.x * w0.w + a.y * w1.w + a.z * w2.w + a.w * w3.w;
        }
    }

    float4 bb = b4[tx];
    #pragma unroll
    for (int rr = 0; rr < 8; rr++) {
        int gr = row0 + ty + rr * 8;
        if (gr < N_NODES) {
            float4 o;
            o.x = fmaxf(acc[rr][0] + bb.x, 0.f);
            o.y = fmaxf(acc[rr][1] + bb.y, 0.f);
            o.z = fmaxf(acc[rr][2] + bb.z, 0.f);
            o.w = fmaxf(acc[rr][3] + bb.w, 0.f);
            ((float4*)g_h)[(size_t)gr * 32 + tx] = o;
        }
    }
}

// ---------------- fused layer 2: agg(g_h,128) + GEMM(K=128) + mean-pool ------
__global__ void __launch_bounds__(256) k_fused2(const float4* __restrict__ W4,
                                                const float4* __restrict__ b4,
                                                const int* __restrict__ batch) {
    __shared__ __align__(16) float4 sA[64 * 32];   // 32 KB
    __shared__ __align__(16) float4 sW[32 * 32];   // 16 KB
    int t = threadIdx.x, lane = t & 31, w = t >> 5;
    int row0 = blockIdx.x * 64;
    const float4* H = (const float4*)g_h;

    #pragma unroll 1
    for (int it = 0; it < 8; it++) {
        int n = row0 + it * 8 + w;
        if (n < N_NODES) {
            float dn = g_dinv[n];
            float4 v = H[(size_t)n * 32 + lane];
            float4 acc;
            acc.x = dn * v.x; acc.y = dn * v.y; acc.z = dn * v.z; acc.w = dn * v.w;
            int e  = g_off[n];
            int e1 = g_off[n + 1];
            for (; e + 1 < e1; e += 2) {
                int s0 = g_csr[e], s1 = g_csr[e + 1];
                float d0 = g_dinv[s0], d1 = g_dinv[s1];
                float4 v0 = H[(size_t)s0 * 32 + lane];
                float4 v1 = H[(size_t)s1 * 32 + lane];
                acc.x += d0 * v0.x + d1 * v1.x;
                acc.y += d0 * v0.y + d1 * v1.y;
                acc.z += d0 * v0.z + d1 * v1.z;
                acc.w += d0 * v0.w + d1 * v1.w;
            }
            if (e < e1) {
                int s0 = g_csr[e];
                float d0 = g_dinv[s0];
                float4 v0 = H[(size_t)s0 * 32 + lane];
                acc.x += d0 * v0.x; acc.y += d0 * v0.y; acc.z += d0 * v0.z; acc.w += d0 * v0.w;
            }
            acc.x *= dn; acc.y *= dn; acc.z *= dn; acc.w *= dn;
            sA[(it * 8 + w) * 32 + lane] = acc;
        } else {
            sA[(it * 8 + w) * 32 + lane] = make_float4(0.f, 0.f, 0.f, 0.f);
        }
    }

    int tx = t & 31, ty = t >> 5;
    float acc[8][4];
    #pragma unroll
    for (int rr = 0; rr < 8; rr++)
        #pragma unroll
        for (int cc = 0; cc < 4; cc++) acc[rr][cc] = 0.f;

    for (int kt = 0; kt < 128; kt += 32) {
        __syncthreads();
        for (int i = t; i < 32 * 32; i += 256) sW[i] = W4[kt * 32 + i];
        __syncthreads();
        #pragma unroll
        for (int k4 = 0; k4 < 8; k4++) {
            float4 w0 = sW[(k4 * 4 + 0) * 32 + tx];
            float4 w1 = sW[(k4 * 4 + 1) * 32 + tx];
            float4 w2 = sW[(k4 * 4 + 2) * 32 + tx];
            float4 w3 = sW[(k4 * 4 + 3) * 32 + tx];
            #pragma unroll
            for (int rr = 0; rr < 8; rr++) {
                float4 a = sA[(ty + rr * 8) * 32 + (kt >> 2) + k4];
                acc[rr][0] += a.x * w0.x + a.y * w1.x + a.z * w2.x + a.w * w3.x;
                acc[rr][1] += a.x * w0.y + a.y * w1.y + a.z * w2.y + a.w * w3.y;
                acc[rr][2] += a.x * w0.z + a.y * w1.z + a.z * w2.z + a.w * w3.z;
                acc[rr][3] += a.x * w0.w + a.y * w1.w + a.z * w2.w + a.w * w3.w;
            }
        }
    }
    __syncthreads();

    float4 bb = b4[tx];
    #pragma unroll
    for (int rr = 0; rr < 8; rr++) {
        float4 o;
        o.x = acc[rr][0] + bb.x;
        o.y = acc[rr][1] + bb.y;
        o.z = acc[rr][2] + bb.z;
        o.w = acc[rr][3] + bb.w;
        sA[(ty + rr * 8) * 32 + tx] = o;
    }
    __syncthreads();

    const float* sAf = (const float*)sA;
    int j = t & 127, half = t >> 7;
    int rbeg = half * 32;
    int rend = min(rbeg + 32, N_NODES - row0);
    float pacc = 0.f;
    int cur = -1, cnt = 0;
    for (int r = rbeg; r < rend; r++) {
        int b = __ldg(&batch[row0 + r]);
        if (b != cur) {
            if (cur >= 0) {
                atomicAdd(&g_pool[cur * HID + j], pacc);
                if (j == 0) atomicAdd(&g_gcnt[cur], (float)cnt);
            }
            cur = b; pacc = 0.f; cnt = 0;
        }
        pacc += sAf[r * 128 + j];
        cnt++;
    }
    if (cur >= 0) {
        atomicAdd(&g_pool[cur * HID + j], pacc);
        if (j == 0) atomicAdd(&g_gcnt[cur], (float)cnt);
    }
}

// ---------------- fused MLP head ----------------
__global__ void __launch_bounds__(128) k_mlp(const float* __restrict__ Wm1,
                                             const float* __restrict__ bm1,
                                             const float* __restrict__ Wm2,
                                             const float* __restrict__ bm2,
                                             float* __restrict__ out) {
    __shared__ float grow[HID];
    __shared__ float r0[HID], r1[HID];
    int r = blockIdx.x;
    int j = threadIdx.x;
    grow[j] = g_pool[r * HID + j] / fmaxf(g_gcnt[r], 1.0f);
    __syncthreads();
    float acc = bm1[j];
    #pragma unroll 8
    for (int k = 0; k < HID; k++) acc += grow[k] * Wm1[k * HID + j];
    float h = fmaxf(acc, 0.f);
    r0[j] = h * Wm2[j * OUT_C + 0];
    r1[j] = h * Wm2[j * OUT_C + 1];
    __syncthreads();
    #pragma unroll
    for (int s = 64; s > 0; s >>= 1) {
        if (j < s) { r0[j] += r0[j + s]; r1[j] += r1[j + s]; }
        __syncthreads();
    }
    if (j == 0) {
        out[r * OUT_C + 0] = r0[0] + bm2[0];
        out[r * OUT_C + 1] = r1[0] + bm2[1];
    }
}

// ---------------- launch ----------------
static inline int cdiv(int a, int b) { return (a + b - 1) / b; }

extern "C" void kernel_launch(void* const* d_in, const int* in_sizes, int n_in,
                              void* d_out, int out_size) {
    const float* x    = (const float*)d_in[0];
    const int*   ei   = (const int*)d_in[1];
    const int*   src  = ei;
    const int*   dst  = ei + N_EDGES;
    const int*   batch= (const int*)d_in[2];
    const float* W1  = (const float*)d_in[3];
    const float* b1  = (const float*)d_in[4];
    const float* W2  = (const float*)d_in[5];
    const float* b2  = (const float*)d_in[6];
    const float* Wm1 = (const float*)d_in[7];
    const float* bm1 = (const float*)d_in[8];
    const float* Wm2 = (const float*)d_in[9];
    const float* bm2 = (const float*)d_in[10];
    float* out = (float*)d_out;

    const int T = 256;

    k_zero    <<<cdiv(N_NODES, T), T>>>();
    k_deg4    <<<cdiv(N_EDGES / 4, T), T>>>(dst);
    k_blocksum<<<SCAN_NBLK, 1024>>>();
    k_scanpart<<<1, 64>>>();
    k_offsets <<<SCAN_NBLK, 1024>>>();
    k_csr4    <<<cdiv(N_EDGES / 4, T), T>>>(src, dst);

    k_fused1<<<cdiv(N_NODES, 64), 256>>>((const float4*)x, (const float4*)W1,
                                         (const float4*)b1);
    k_fused2<<<cdiv(N_NODES, 64), 256>>>((const float4*)W2, (const float4*)b2, batch);

    k_mlp<<<N_GRAPHS, HID>>>(Wm1, bm1, Wm2, bm2, out);
}